// round 15
// baseline (speedup 1.0000x reference)
#include <cuda_runtime.h>
#include <cuda.h>
#include <cuda_fp16.h>
#include <cstdint>

// ---------------- problem constants ----------------
#define Nn 4096
#define Mm 4096
#define Dd 1024

// ---------------- GEMM tiling (round-11 champion shape) ----------------
#define BM 128
#define BN 128
#define BK 64                      // 64 fp16 = 128B rows (SW128 atom width)
#define KT (Dd / BK)               // 16 iterations
#define NSPLIT 32
#define STAGES 3
#define NCW 16                     // consumer warps (4m x 4n of 32x32 tiles)
#define NW 17
#define THREADS (NW * 32)          // 544

#define A_SZ (BM * 128)            // 16384 B
#define B_SZ (BN * 128)            // 16384 B
#define STG (A_SZ + B_SZ)          // 32768 B
#define DYN_SMEM (STAGES * STG + 1024)

// ---------------- scratch ----------------
__device__ __align__(256) __half g_zb[Nn * Dd];
__device__ __align__(256) __half g_eb[Mm * Dd];
__device__ __align__(256) float g_zsq[Nn];
__device__ __align__(256) unsigned g_rowmin[Mm];   // packed (valbits | 12-bit col)
__device__ unsigned g_mcnt[Mm / BM];               // per-m-block completion counters
__device__ unsigned long long g_acc;
__device__ unsigned g_done;

// ---------------- PTX helpers ----------------
#define MBARRIER_INIT(addr, cnt) \
    asm volatile("mbarrier.init.shared.b64 [%0], %1;" ::"r"(addr), "r"(cnt) : "memory")
#define MBARRIER_EXPECT_TX(addr, bytes) \
    asm volatile("mbarrier.arrive.expect_tx.shared.b64 _, [%0], %1;" ::"r"(addr), "r"(bytes) : "memory")
#define MBARRIER_ARRIVE(addr) \
    asm volatile("mbarrier.arrive.shared.b64 _, [%0];" ::"r"(addr) : "memory")

__device__ __forceinline__ void mbar_wait(uint32_t addr, uint32_t parity) {
    asm volatile(
        "{\n\t.reg .pred P;\n\t"
        "WL%=:\n\t"
        "mbarrier.try_wait.parity.acquire.cta.shared::cta.b64 P, [%0], %1, 0x989680;\n\t"
        "@P bra.uni WD%=;\n\t"
        "bra.uni WL%=;\n\t"
        "WD%=:\n\t}"
        ::"r"(addr), "r"(parity) : "memory");
}
__device__ __forceinline__ void mbar_wait_relaxed(uint32_t addr, uint32_t parity) {
    asm volatile(
        "{\n\t.reg .pred P;\n\t"
        "WL%=:\n\t"
        "mbarrier.try_wait.parity.relaxed.cta.shared::cta.b64 P, [%0], %1, 0x989680;\n\t"
        "@P bra.uni WD%=;\n\t"
        "bra.uni WL%=;\n\t"
        "WD%=:\n\t}"
        ::"r"(addr), "r"(parity) : "memory");
}

__device__ __forceinline__ void tma_load_2d(uint32_t smem_addr, const void* map,
                                            int cx, int cy, uint32_t mbar) {
    asm volatile(
        "cp.async.bulk.tensor.2d.shared::cta.global.tile.mbarrier::complete_tx::bytes "
        "[%0], [%1, {%2, %3}], [%4];"
        ::"r"(smem_addr), "l"(map), "r"(cx), "r"(cy), "r"(mbar)
        : "memory");
}

__device__ __forceinline__ void ldsm4(uint32_t* r, uint32_t saddr) {
    asm volatile("ldmatrix.sync.aligned.m8n8.x4.shared.b16 {%0,%1,%2,%3}, [%4];\n"
                 : "=r"(r[0]), "=r"(r[1]), "=r"(r[2]), "=r"(r[3])
                 : "r"(saddr));
}
__device__ __forceinline__ void mma16816_f16(uint32_t* c, const uint32_t* a,
                                             uint32_t b0, uint32_t b1) {
    asm volatile(
        "mma.sync.aligned.m16n8k16.row.col.f16.f16.f16.f16 "
        "{%0,%1}, {%2,%3,%4,%5}, {%6,%7}, {%0,%1};\n"
        : "+r"(c[0]), "+r"(c[1])
        : "r"(a[0]), "r"(a[1]), "r"(a[2]), "r"(a[3]), "r"(b0), "r"(b1));
}

// swizzled smem address of 16B chunk (row, cc) in a 128B-row SW128 tile
__device__ __forceinline__ uint32_t swz(uint32_t base, int row, int cc) {
    return base + ((uint32_t)row << 7) + (((uint32_t)(cc ^ (row & 7))) << 4);
}

// pack selection key: positive float bits (top 20) | 12-bit column
__device__ __forceinline__ unsigned packkey(float v, int col) {
    return (__float_as_uint(v) & 0xFFFFF000u) | (unsigned)col;
}

// ================= kernel 1: convert(fp16) + z norms + state init ==========
__global__ void __launch_bounds__(256) convert_kernel(const float* __restrict__ z,
                                                      const float* __restrict__ e) {
    if (blockIdx.x == 0) {
#pragma unroll
        for (int i = 0; i < Mm / 256; i++) g_rowmin[threadIdx.x + 256 * i] = 0xFFFFFFFFu;
        if (threadIdx.x < Mm / BM) g_mcnt[threadIdx.x] = 0u;
        if (threadIdx.x == 0) { g_acc = 0ull; g_done = 0u; }
    }
    const int gwarp = (blockIdx.x * 256 + threadIdx.x) >> 5;
    const int lane = threadIdx.x & 31;
    const float* src;
    __half* dst;
    float* sqo = nullptr;
    if (gwarp < Nn) {
        src = z + (size_t)gwarp * Dd;
        dst = g_zb + (size_t)gwarp * Dd;
        sqo = g_zsq + gwarp;
    } else {
        const int r = gwarp - Nn;
        src = e + (size_t)r * Dd;
        dst = g_eb + (size_t)r * Dd;
    }
    const float4* s4 = reinterpret_cast<const float4*>(src);
    uint4* d4 = reinterpret_cast<uint4*>(dst);
    float4 v[8];
#pragma unroll
    for (int i = 0; i < 8; i++) v[i] = s4[2 * (lane + 32 * (i >> 1)) + (i & 1)];
    float s = 0.f;
#pragma unroll
    for (int i = 0; i < 4; i++) {
        const int idx = lane + 32 * i;
        const float4 v0 = v[2 * i];
        const float4 v1 = v[2 * i + 1];
        __half2 p0 = __floats2half2_rn(v0.x, v0.y);
        __half2 p1 = __floats2half2_rn(v0.z, v0.w);
        __half2 p2 = __floats2half2_rn(v1.x, v1.y);
        __half2 p3 = __floats2half2_rn(v1.z, v1.w);
        uint4 w;
        w.x = *reinterpret_cast<unsigned*>(&p0);
        w.y = *reinterpret_cast<unsigned*>(&p1);
        w.z = *reinterpret_cast<unsigned*>(&p2);
        w.w = *reinterpret_cast<unsigned*>(&p3);
        d4[idx] = w;
        s += v0.x * v0.x + v0.y * v0.y + v0.z * v0.z + v0.w * v0.w;
        s += v1.x * v1.x + v1.y * v1.y + v1.z * v1.z + v1.w * v1.w;
    }
    if (sqo) {
#pragma unroll
        for (int o = 16; o; o >>= 1) s += __shfl_xor_sync(0xffffffffu, s, o);
        if (lane == 0) *sqo = s;
    }
}

// ================= kernel 2: TMA-fed f16-acc GEMM + argmin + fused exact rerank =====
// Round-11 champion mainloop. New: the CTA that completes each m-block (all 32
// n-splits done) immediately reranks its 128 rows exactly (fp32) and accumulates
// the deterministic fixed-point sum; last m-block writes the mean.
__global__ void __launch_bounds__(THREADS, 2) gemm_min_kernel(
    const __grid_constant__ CUtensorMap tmA,
    const __grid_constant__ CUtensorMap tmB,
    const float* __restrict__ zf, const float* __restrict__ ef,
    float* __restrict__ out) {
    extern __shared__ char dyn_raw[];
    __shared__ __align__(8) uint64_t s_bar[2 * STAGES];
    __shared__ unsigned srm[4][BM];
    __shared__ float wsum[NW];
    __shared__ unsigned s_flag;

    uint32_t dynb = (uint32_t)__cvta_generic_to_shared(dyn_raw);
    dynb = (dynb + 1023u) & ~1023u;
    const uint32_t barb = (uint32_t)__cvta_generic_to_shared(s_bar);
#define BAR_FULL(s) (barb + (uint32_t)(s) * 8u)
#define BAR_EMPTY(s) (barb + (uint32_t)(STAGES + (s)) * 8u)

    const int tid = threadIdx.x;
    const int lane = tid & 31;
    const int warp = tid >> 5;

    const int mblk = blockIdx.x;
    const int m0 = mblk * BM;
    const int n0 = blockIdx.y * BN;

    if (tid == 0) {
#pragma unroll
        for (int s = 0; s < STAGES; s++) {
            MBARRIER_INIT(BAR_FULL(s), 1);
            MBARRIER_INIT(BAR_EMPTY(s), NCW);
        }
    }
    __syncthreads();

    if (warp < NCW) {
        // ---------------- consumers (round-11 exact) ----------------
        const int wm = warp >> 2;        // 0..3 : 32-row group
        const int wn = warp & 3;         // 0..3 : 32-col group
        const int ldrow = lane & 15;
        const int ldcc = lane >> 4;

        uint32_t acc[2][4][2];           // f16x2 accumulators (16 regs)
#pragma unroll
        for (int mi = 0; mi < 2; mi++)
#pragma unroll
            for (int g = 0; g < 4; g++) { acc[mi][g][0] = 0u; acc[mi][g][1] = 0u; }

        int slot = 0, ph = 0;
        for (int j = 0; j < KT; j++) {
            mbar_wait(BAR_FULL(slot), (uint32_t)ph);
            const uint32_t sa = dynb + slot * STG;
            const uint32_t sb = sa + A_SZ;

#pragma unroll
            for (int ks = 0; ks < 4; ks++) {
                const int cc = ks * 2 + ldcc;
                uint32_t a[2][4];
#pragma unroll
                for (int mi = 0; mi < 2; mi++)
                    ldsm4(a[mi], swz(sa, wm * 32 + mi * 16 + ldrow, cc));
                uint32_t b[2][4];
#pragma unroll
                for (int h = 0; h < 2; h++)
                    ldsm4(b[h], swz(sb, wn * 32 + h * 16 + ldrow, cc));
#pragma unroll
                for (int h = 0; h < 2; h++) {
#pragma unroll
                    for (int mi = 0; mi < 2; mi++) {
                        mma16816_f16(&acc[mi][2 * h][0], a[mi], b[h][0], b[h][2]);
                        mma16816_f16(&acc[mi][2 * h + 1][0], a[mi], b[h][1], b[h][3]);
                    }
                }
            }
            __syncwarp();
            if (lane == 0) MBARRIER_ARRIVE(BAR_EMPTY(slot));
            if (++slot == STAGES) { slot = 0; ph ^= 1; }
        }

        // ---- epilogue: packed argmin keys over this CTA's 128 columns ----
        unsigned rk0 = 0xFFFFFFFFu, rk1 = 0xFFFFFFFFu, rk2 = 0xFFFFFFFFu, rk3 = 0xFFFFFFFFu;
        const int colbase = n0 + wn * 32 + (lane & 3) * 2;
#pragma unroll
        for (int g = 0; g < 4; g++) {
            const int col = colbase + g * 8;
            const float zs0 = g_zsq[col] + 1024.f;   // shift keeps v positive
            const float zs1 = g_zsq[col + 1] + 1024.f;
#pragma unroll
            for (int mi = 0; mi < 2; mi++) {
                const __half2 h0 = *reinterpret_cast<const __half2*>(&acc[mi][g][0]);
                const __half2 h1 = *reinterpret_cast<const __half2*>(&acc[mi][g][1]);
                const unsigned kA = min(packkey(fmaf(-2.f, __low2float(h0), zs0), col),
                                        packkey(fmaf(-2.f, __high2float(h0), zs1), col + 1));
                const unsigned kB = min(packkey(fmaf(-2.f, __low2float(h1), zs0), col),
                                        packkey(fmaf(-2.f, __high2float(h1), zs1), col + 1));
                if (mi == 0) { rk0 = min(rk0, kA); rk1 = min(rk1, kB); }
                else         { rk2 = min(rk2, kA); rk3 = min(rk3, kB); }
            }
        }
#pragma unroll
        for (int off = 1; off <= 2; off <<= 1) {
            rk0 = min(rk0, __shfl_xor_sync(0xffffffffu, rk0, off));
            rk1 = min(rk1, __shfl_xor_sync(0xffffffffu, rk1, off));
            rk2 = min(rk2, __shfl_xor_sync(0xffffffffu, rk2, off));
            rk3 = min(rk3, __shfl_xor_sync(0xffffffffu, rk3, off));
        }
        if ((lane & 3) == 0) {
            const int q = lane >> 2;
            srm[wn][wm * 32 + q] = rk0;
            srm[wn][wm * 32 + q + 8] = rk1;
            srm[wn][wm * 32 + 16 + q] = rk2;
            srm[wn][wm * 32 + 24 + q] = rk3;
        }
    } else if (lane == 0) {
        // ---------------- producer (warp 16, lane 0) ----------------
        int slot = 0, ph = 1;
        for (int j = 0; j < KT; j++) {
            mbar_wait_relaxed(BAR_EMPTY(slot), (uint32_t)ph);
            MBARRIER_EXPECT_TX(BAR_FULL(slot), STG);
            const uint32_t sa = dynb + slot * STG;
            tma_load_2d(sa, &tmA, j * BK, m0, BAR_FULL(slot));
            tma_load_2d(sa + A_SZ, &tmB, j * BK, n0, BAR_FULL(slot));
            if (++slot == STAGES) { slot = 0; ph ^= 1; }
        }
    }

    __syncthreads();
    if (tid < BM) {
        const unsigned k = min(min(srm[0][tid], srm[1][tid]), min(srm[2][tid], srm[3][tid]));
        atomicMin(&g_rowmin[m0 + tid], k);
    }

    // ---- per-m-block completion; last CTA of the block reranks its 128 rows ----
    __threadfence();
    __syncthreads();
    if (tid == 0) s_flag = atomicAdd(&g_mcnt[mblk], 1u);
    __syncthreads();
    if (s_flag == NSPLIT - 1) {
        __threadfence();
        // exact fp32 rerank: warp w handles rows m0 + w + 17*i
        float wacc = 0.f;
        for (int r = warp; r < BM; r += NW) {
            const int m = m0 + r;
            const int col = (int)(g_rowmin[m] & 0xFFFu);
            const float4* zp = reinterpret_cast<const float4*>(zf + (size_t)col * Dd);
            const float4* ep = reinterpret_cast<const float4*>(ef + (size_t)m * Dd);
            float d = 0.f;
#pragma unroll
            for (int i = 0; i < 8; i++) {
                const float4 a = zp[lane + 32 * i];
                const float4 b = ep[lane + 32 * i];
                const float dx = a.x - b.x, dy = a.y - b.y, dz = a.z - b.z, dw = a.w - b.w;
                d += dx * dx + dy * dy + dz * dz + dw * dw;
            }
            wacc += d;
        }
#pragma unroll
        for (int o = 16; o; o >>= 1) wacc += __shfl_xor_sync(0xffffffffu, wacc, o);
        if (lane == 0) wsum[warp] = wacc;
        __syncthreads();
        if (tid == 0) {
            float blk = 0.f;
#pragma unroll
            for (int i = 0; i < NW; i++) blk += wsum[i];
            // deterministic fixed-point accumulation (2^-24)
            atomicAdd(&g_acc, (unsigned long long)__double2ll_rn((double)blk * 16777216.0));
            __threadfence();
            const unsigned done = atomicAdd(&g_done, 1u);
            if (done == (Mm / BM) - 1) {
                const unsigned long long tot = atomicAdd(&g_acc, 0ull);
                out[0] = (float)((double)tot / 16777216.0 / (double)Mm);
            }
        }
    }
}

// ================= host side =================
typedef CUresult (*EncodeTiledFn)(CUtensorMap*, CUtensorMapDataType, cuuint32_t, void*,
                                  const cuuint64_t*, const cuuint64_t*, const cuuint32_t*,
                                  const cuuint32_t*, CUtensorMapInterleave, CUtensorMapSwizzle,
                                  CUtensorMapL2promotion, CUtensorMapFloatOOBfill);

static void encode_map(EncodeTiledFn fn, CUtensorMap* tm, void* base) {
    cuuint64_t dims[2] = {(cuuint64_t)Dd, (cuuint64_t)Nn};
    cuuint64_t strides[1] = {(cuuint64_t)Dd * 2};
    cuuint32_t box[2] = {(cuuint32_t)BK, (cuuint32_t)BM};
    cuuint32_t estr[2] = {1, 1};
    fn(tm, CU_TENSOR_MAP_DATA_TYPE_FLOAT16, 2, base, dims, strides, box, estr,
       CU_TENSOR_MAP_INTERLEAVE_NONE, CU_TENSOR_MAP_SWIZZLE_128B,
       CU_TENSOR_MAP_L2_PROMOTION_L2_128B, CU_TENSOR_MAP_FLOAT_OOB_FILL_NONE);
}

extern "C" void kernel_launch(void* const* d_in, const int* in_sizes, int n_in,
                              void* d_out, int out_size) {
    const float* z = (const float*)d_in[0];  // [4096, 1024]
    const float* e = (const float*)d_in[1];  // [4096, 1024]
    float* out = (float*)d_out;              // [1]

    EncodeTiledFn enc = nullptr;
    {
        void* fn = nullptr;
#if CUDART_VERSION >= 12050
        cudaDriverEntryPointQueryResult qr;
        cudaGetDriverEntryPointByVersion("cuTensorMapEncodeTiled", &fn, 12000,
                                         cudaEnableDefault, &qr);
#else
        cudaGetDriverEntryPoint("cuTensorMapEncodeTiled", &fn, cudaEnableDefault);
#endif
        enc = (EncodeTiledFn)fn;
    }
    void *pe = nullptr, *pz = nullptr;
    cudaGetSymbolAddress(&pe, g_eb);
    cudaGetSymbolAddress(&pz, g_zb);
    CUtensorMap tmA, tmB;
    encode_map(enc, &tmA, pe);
    encode_map(enc, &tmB, pz);

    convert_kernel<<<(Nn + Mm) / 8, 256>>>(z, e);

    static bool attr_set = false;
    if (!attr_set) {
        cudaFuncSetAttribute(gemm_min_kernel, cudaFuncAttributeMaxDynamicSharedMemorySize,
                             DYN_SMEM);
        attr_set = true;
    }
    dim3 grid(Mm / BM, NSPLIT);  // 32 x 32 = 1024 CTAs
    gemm_min_kernel<<<grid, THREADS, DYN_SMEM>>>(tmA, tmB, z, e, out);
}

// round 16
// speedup vs baseline: 1.0588x; 1.0588x over previous
#include <cuda_runtime.h>
#include <cuda.h>
#include <cuda_fp16.h>
#include <cstdint>

// ---------------- problem constants ----------------
#define Nn 4096
#define Mm 4096
#define Dd 1024

// ---------------- GEMM tiling (round-11 champion shape) ----------------
#define BM 128
#define BN 128
#define BK 64                      // 64 fp16 = 128B rows (SW128 atom width)
#define KT (Dd / BK)               // 16 iterations
#define NSPLIT 32
#define STAGES 3
#define NCW 16                     // consumer warps (4m x 4n of 32x32 tiles)
#define THREADS (NCW * 32 + 32)    // +1 producer warp = 544

#define A_SZ (BM * 128)            // 16384 B
#define B_SZ (BN * 128)            // 16384 B
#define STG (A_SZ + B_SZ)          // 32768 B
#define DYN_SMEM (STAGES * STG + 1024)

// ---------------- scratch ----------------
__device__ __align__(256) __half g_zb[Nn * Dd];
__device__ __align__(256) __half g_eb[Mm * Dd];
__device__ __align__(256) float g_zsq[Nn];
__device__ __align__(256) unsigned g_rowmin[Mm];   // packed (valbits | 12-bit col)
__device__ unsigned long long g_acc;
__device__ unsigned g_cnt;

// ---------------- PTX helpers ----------------
#define MBARRIER_INIT(addr, cnt) \
    asm volatile("mbarrier.init.shared.b64 [%0], %1;" ::"r"(addr), "r"(cnt) : "memory")
#define MBARRIER_EXPECT_TX(addr, bytes) \
    asm volatile("mbarrier.arrive.expect_tx.shared.b64 _, [%0], %1;" ::"r"(addr), "r"(bytes) : "memory")
#define MBARRIER_ARRIVE(addr) \
    asm volatile("mbarrier.arrive.shared.b64 _, [%0];" ::"r"(addr) : "memory")

__device__ __forceinline__ void mbar_wait(uint32_t addr, uint32_t parity) {
    asm volatile(
        "{\n\t.reg .pred P;\n\t"
        "WL%=:\n\t"
        "mbarrier.try_wait.parity.acquire.cta.shared::cta.b64 P, [%0], %1, 0x989680;\n\t"
        "@P bra.uni WD%=;\n\t"
        "bra.uni WL%=;\n\t"
        "WD%=:\n\t}"
        ::"r"(addr), "r"(parity) : "memory");
}
__device__ __forceinline__ void mbar_wait_relaxed(uint32_t addr, uint32_t parity) {
    asm volatile(
        "{\n\t.reg .pred P;\n\t"
        "WL%=:\n\t"
        "mbarrier.try_wait.parity.relaxed.cta.shared::cta.b64 P, [%0], %1, 0x989680;\n\t"
        "@P bra.uni WD%=;\n\t"
        "bra.uni WL%=;\n\t"
        "WD%=:\n\t}"
        ::"r"(addr), "r"(parity) : "memory");
}

__device__ __forceinline__ void tma_load_2d(uint32_t smem_addr, const void* map,
                                            int cx, int cy, uint32_t mbar) {
    asm volatile(
        "cp.async.bulk.tensor.2d.shared::cta.global.tile.mbarrier::complete_tx::bytes "
        "[%0], [%1, {%2, %3}], [%4];"
        ::"r"(smem_addr), "l"(map), "r"(cx), "r"(cy), "r"(mbar)
        : "memory");
}

__device__ __forceinline__ void ldsm4(uint32_t* r, uint32_t saddr) {
    asm volatile("ldmatrix.sync.aligned.m8n8.x4.shared.b16 {%0,%1,%2,%3}, [%4];\n"
                 : "=r"(r[0]), "=r"(r[1]), "=r"(r[2]), "=r"(r[3])
                 : "r"(saddr));
}
__device__ __forceinline__ void mma16816_f16(uint32_t* c, const uint32_t* a,
                                             uint32_t b0, uint32_t b1) {
    asm volatile(
        "mma.sync.aligned.m16n8k16.row.col.f16.f16.f16.f16 "
        "{%0,%1}, {%2,%3,%4,%5}, {%6,%7}, {%0,%1};\n"
        : "+r"(c[0]), "+r"(c[1])
        : "r"(a[0]), "r"(a[1]), "r"(a[2]), "r"(a[3]), "r"(b0), "r"(b1));
}

// swizzled smem address of 16B chunk (row, cc) in a 128B-row SW128 tile
__device__ __forceinline__ uint32_t swz(uint32_t base, int row, int cc) {
    return base + ((uint32_t)row << 7) + (((uint32_t)(cc ^ (row & 7))) << 4);
}

// pack selection key: positive float bits (top 20) | 12-bit column
__device__ __forceinline__ unsigned packkey(float v, int col) {
    return (__float_as_uint(v) & 0xFFFFF000u) | (unsigned)col;
}

// ================= kernel 1: convert(fp16) + z norms + state init ==========
__global__ void __launch_bounds__(256) convert_kernel(const float* __restrict__ z,
                                                      const float* __restrict__ e) {
    if (blockIdx.x == 0) {
#pragma unroll
        for (int i = 0; i < Mm / 256; i++) g_rowmin[threadIdx.x + 256 * i] = 0xFFFFFFFFu;
        if (threadIdx.x == 0) { g_acc = 0ull; g_cnt = 0u; }
    }
    const int gwarp = (blockIdx.x * 256 + threadIdx.x) >> 5;
    const int lane = threadIdx.x & 31;
    const float* src;
    __half* dst;
    float* sqo = nullptr;
    if (gwarp < Nn) {
        src = z + (size_t)gwarp * Dd;
        dst = g_zb + (size_t)gwarp * Dd;
        sqo = g_zsq + gwarp;
    } else {
        const int r = gwarp - Nn;
        src = e + (size_t)r * Dd;
        dst = g_eb + (size_t)r * Dd;
    }
    const float4* s4 = reinterpret_cast<const float4*>(src);
    uint4* d4 = reinterpret_cast<uint4*>(dst);
    float4 v[8];
#pragma unroll
    for (int i = 0; i < 8; i++) v[i] = s4[2 * (lane + 32 * (i >> 1)) + (i & 1)];
    float s = 0.f;
#pragma unroll
    for (int i = 0; i < 4; i++) {
        const int idx = lane + 32 * i;
        const float4 v0 = v[2 * i];
        const float4 v1 = v[2 * i + 1];
        __half2 p0 = __floats2half2_rn(v0.x, v0.y);
        __half2 p1 = __floats2half2_rn(v0.z, v0.w);
        __half2 p2 = __floats2half2_rn(v1.x, v1.y);
        __half2 p3 = __floats2half2_rn(v1.z, v1.w);
        uint4 w;
        w.x = *reinterpret_cast<unsigned*>(&p0);
        w.y = *reinterpret_cast<unsigned*>(&p1);
        w.z = *reinterpret_cast<unsigned*>(&p2);
        w.w = *reinterpret_cast<unsigned*>(&p3);
        d4[idx] = w;
        s += v0.x * v0.x + v0.y * v0.y + v0.z * v0.z + v0.w * v0.w;
        s += v1.x * v1.x + v1.y * v1.y + v1.z * v1.z + v1.w * v1.w;
    }
    if (sqo) {
#pragma unroll
        for (int o = 16; o; o >>= 1) s += __shfl_xor_sync(0xffffffffu, s, o);
        if (lane == 0) *sqo = s;
    }
}

// ================= kernel 2: TMA-fed f16-acc GEMM + packed argmin =================
// Round-11 champion + in-register fragment double-buffering: per ks step the next
// step's fragments load into the alternate buffer before this step's mma burst,
// hiding the ldsm->mma scoreboard latency. 48 data regs peak (<60 cap).
__global__ void __launch_bounds__(THREADS, 2) gemm_min_kernel(
    const __grid_constant__ CUtensorMap tmA,
    const __grid_constant__ CUtensorMap tmB) {
    extern __shared__ char dyn_raw[];
    __shared__ __align__(8) uint64_t s_bar[2 * STAGES];
    __shared__ unsigned srm[4][BM];

    uint32_t dynb = (uint32_t)__cvta_generic_to_shared(dyn_raw);
    dynb = (dynb + 1023u) & ~1023u;
    const uint32_t barb = (uint32_t)__cvta_generic_to_shared(s_bar);
#define BAR_FULL(s) (barb + (uint32_t)(s) * 8u)
#define BAR_EMPTY(s) (barb + (uint32_t)(STAGES + (s)) * 8u)

    const int tid = threadIdx.x;
    const int lane = tid & 31;
    const int warp = tid >> 5;

    const int m0 = blockIdx.x * BM;
    const int n0 = blockIdx.y * BN;

    if (tid == 0) {
#pragma unroll
        for (int s = 0; s < STAGES; s++) {
            MBARRIER_INIT(BAR_FULL(s), 1);
            MBARRIER_INIT(BAR_EMPTY(s), NCW);
        }
    }
    __syncthreads();

    if (warp < NCW) {
        // ---------------- consumers ----------------
        const int wm = warp >> 2;        // 0..3 : 32-row group
        const int wn = warp & 3;         // 0..3 : 32-col group
        const int ldrow = lane & 15;
        const int ldcc = lane >> 4;

        uint32_t acc[2][4][2];           // f16x2 accumulators (16 regs)
#pragma unroll
        for (int mi = 0; mi < 2; mi++)
#pragma unroll
            for (int g = 0; g < 4; g++) { acc[mi][g][0] = 0u; acc[mi][g][1] = 0u; }

        uint32_t fa[2][2][4];            // [buf][mi][frag] : 16 regs
        uint32_t fb[2][2][4];            // [buf][h][frag]  : 16 regs

        int slot = 0, ph = 0;
        for (int j = 0; j < KT; j++) {
            mbar_wait(BAR_FULL(slot), (uint32_t)ph);
            const uint32_t sa = dynb + slot * STG;
            const uint32_t sb = sa + A_SZ;

            // prime ks=0 fragments into buffer 0
            {
                const int cc = ldcc;
#pragma unroll
                for (int mi = 0; mi < 2; mi++)
                    ldsm4(fa[0][mi], swz(sa, wm * 32 + mi * 16 + ldrow, cc));
#pragma unroll
                for (int h = 0; h < 2; h++)
                    ldsm4(fb[0][h], swz(sb, wn * 32 + h * 16 + ldrow, cc));
            }
#pragma unroll
            for (int ks = 0; ks < 4; ks++) {
                const int cur = ks & 1;
                if (ks < 3) {            // prefetch ks+1 into the alternate buffer
                    const int cc = (ks + 1) * 2 + ldcc;
#pragma unroll
                    for (int mi = 0; mi < 2; mi++)
                        ldsm4(fa[cur ^ 1][mi], swz(sa, wm * 32 + mi * 16 + ldrow, cc));
#pragma unroll
                    for (int h = 0; h < 2; h++)
                        ldsm4(fb[cur ^ 1][h], swz(sb, wn * 32 + h * 16 + ldrow, cc));
                }
#pragma unroll
                for (int h = 0; h < 2; h++) {
#pragma unroll
                    for (int mi = 0; mi < 2; mi++) {
                        mma16816_f16(&acc[mi][2 * h][0], fa[cur][mi],
                                     fb[cur][h][0], fb[cur][h][2]);
                        mma16816_f16(&acc[mi][2 * h + 1][0], fa[cur][mi],
                                     fb[cur][h][1], fb[cur][h][3]);
                    }
                }
            }
            __syncwarp();
            if (lane == 0) MBARRIER_ARRIVE(BAR_EMPTY(slot));
            if (++slot == STAGES) { slot = 0; ph ^= 1; }
        }

        // ---- epilogue: packed argmin keys over this CTA's 128 columns ----
        unsigned rk0 = 0xFFFFFFFFu, rk1 = 0xFFFFFFFFu, rk2 = 0xFFFFFFFFu, rk3 = 0xFFFFFFFFu;
        const int colbase = n0 + wn * 32 + (lane & 3) * 2;
#pragma unroll
        for (int g = 0; g < 4; g++) {
            const int col = colbase + g * 8;
            const float zs0 = g_zsq[col] + 1024.f;   // shift keeps v positive
            const float zs1 = g_zsq[col + 1] + 1024.f;
#pragma unroll
            for (int mi = 0; mi < 2; mi++) {
                const __half2 h0 = *reinterpret_cast<const __half2*>(&acc[mi][g][0]);
                const __half2 h1 = *reinterpret_cast<const __half2*>(&acc[mi][g][1]);
                const unsigned kA = min(packkey(fmaf(-2.f, __low2float(h0), zs0), col),
                                        packkey(fmaf(-2.f, __high2float(h0), zs1), col + 1));
                const unsigned kB = min(packkey(fmaf(-2.f, __low2float(h1), zs0), col),
                                        packkey(fmaf(-2.f, __high2float(h1), zs1), col + 1));
                if (mi == 0) { rk0 = min(rk0, kA); rk1 = min(rk1, kB); }
                else         { rk2 = min(rk2, kA); rk3 = min(rk3, kB); }
            }
        }
#pragma unroll
        for (int off = 1; off <= 2; off <<= 1) {
            rk0 = min(rk0, __shfl_xor_sync(0xffffffffu, rk0, off));
            rk1 = min(rk1, __shfl_xor_sync(0xffffffffu, rk1, off));
            rk2 = min(rk2, __shfl_xor_sync(0xffffffffu, rk2, off));
            rk3 = min(rk3, __shfl_xor_sync(0xffffffffu, rk3, off));
        }
        if ((lane & 3) == 0) {
            const int q = lane >> 2;
            srm[wn][wm * 32 + q] = rk0;
            srm[wn][wm * 32 + q + 8] = rk1;
            srm[wn][wm * 32 + 16 + q] = rk2;
            srm[wn][wm * 32 + 24 + q] = rk3;
        }
    } else if (lane == 0) {
        // ---------------- producer (warp 16, lane 0) ----------------
        int slot = 0, ph = 1;
        for (int j = 0; j < KT; j++) {
            mbar_wait_relaxed(BAR_EMPTY(slot), (uint32_t)ph);
            MBARRIER_EXPECT_TX(BAR_FULL(slot), STG);
            const uint32_t sa = dynb + slot * STG;
            tma_load_2d(sa, &tmA, j * BK, m0, BAR_FULL(slot));
            tma_load_2d(sa + A_SZ, &tmB, j * BK, n0, BAR_FULL(slot));
            if (++slot == STAGES) { slot = 0; ph ^= 1; }
        }
    }

    __syncthreads();
    if (tid < BM) {
        const unsigned k = min(min(srm[0][tid], srm[1][tid]), min(srm[2][tid], srm[3][tid]));
        atomicMin(&g_rowmin[m0 + tid], k);
    }
}

// ================= kernel 3: exact rerank + fused deterministic sum =================
__global__ void __launch_bounds__(256) rerank_kernel(const float* __restrict__ z,
                                                     const float* __restrict__ e,
                                                     float* __restrict__ out) {
    const int warp = threadIdx.x >> 5;
    const int lane = threadIdx.x & 31;
    const int m = blockIdx.x * 8 + warp;

    const int col = (int)(g_rowmin[m] & 0xFFFu);
    const float4* zp = reinterpret_cast<const float4*>(z + (size_t)col * Dd);
    const float4* ep = reinterpret_cast<const float4*>(e + (size_t)m * Dd);
    float d = 0.f;
#pragma unroll
    for (int i = 0; i < 8; i++) {
        const float4 a = zp[lane + 32 * i];
        const float4 b = ep[lane + 32 * i];
        const float dx = a.x - b.x, dy = a.y - b.y, dz = a.z - b.z, dw = a.w - b.w;
        d += dx * dx + dy * dy + dz * dz + dw * dw;
    }
#pragma unroll
    for (int o = 16; o; o >>= 1) d += __shfl_xor_sync(0xffffffffu, d, o);

    __shared__ float wsum[8];
    if (lane == 0) wsum[warp] = d;
    __syncthreads();
    if (threadIdx.x == 0) {
        float blk = 0.f;
#pragma unroll
        for (int i = 0; i < 8; i++) blk += wsum[i];
        // deterministic fixed-point accumulation (2^-24)
        atomicAdd(&g_acc, (unsigned long long)__double2ll_rn((double)blk * 16777216.0));
        __threadfence();
        const unsigned done = atomicAdd(&g_cnt, 1u);
        if (done == (Mm / 8) - 1) {
            const unsigned long long tot = atomicAdd(&g_acc, 0ull);
            out[0] = (float)((double)tot / 16777216.0 / (double)Mm);
        }
    }
}

// ================= host side =================
typedef CUresult (*EncodeTiledFn)(CUtensorMap*, CUtensorMapDataType, cuuint32_t, void*,
                                  const cuuint64_t*, const cuuint64_t*, const cuuint32_t*,
                                  const cuuint32_t*, CUtensorMapInterleave, CUtensorMapSwizzle,
                                  CUtensorMapL2promotion, CUtensorMapFloatOOBfill);

static void encode_map(EncodeTiledFn fn, CUtensorMap* tm, void* base) {
    cuuint64_t dims[2] = {(cuuint64_t)Dd, (cuuint64_t)Nn};
    cuuint64_t strides[1] = {(cuuint64_t)Dd * 2};
    cuuint32_t box[2] = {(cuuint32_t)BK, (cuuint32_t)BM};
    cuuint32_t estr[2] = {1, 1};
    fn(tm, CU_TENSOR_MAP_DATA_TYPE_FLOAT16, 2, base, dims, strides, box, estr,
       CU_TENSOR_MAP_INTERLEAVE_NONE, CU_TENSOR_MAP_SWIZZLE_128B,
       CU_TENSOR_MAP_L2_PROMOTION_L2_128B, CU_TENSOR_MAP_FLOAT_OOB_FILL_NONE);
}

extern "C" void kernel_launch(void* const* d_in, const int* in_sizes, int n_in,
                              void* d_out, int out_size) {
    const float* z = (const float*)d_in[0];  // [4096, 1024]
    const float* e = (const float*)d_in[1];  // [4096, 1024]
    float* out = (float*)d_out;              // [1]

    EncodeTiledFn enc = nullptr;
    {
        void* fn = nullptr;
#if CUDART_VERSION >= 12050
        cudaDriverEntryPointQueryResult qr;
        cudaGetDriverEntryPointByVersion("cuTensorMapEncodeTiled", &fn, 12000,
                                         cudaEnableDefault, &qr);
#else
        cudaGetDriverEntryPoint("cuTensorMapEncodeTiled", &fn, cudaEnableDefault);
#endif
        enc = (EncodeTiledFn)fn;
    }
    void *pe = nullptr, *pz = nullptr;
    cudaGetSymbolAddress(&pe, g_eb);
    cudaGetSymbolAddress(&pz, g_zb);
    CUtensorMap tmA, tmB;
    encode_map(enc, &tmA, pe);
    encode_map(enc, &tmB, pz);

    convert_kernel<<<(Nn + Mm) / 8, 256>>>(z, e);

    static bool attr_set = false;
    if (!attr_set) {
        cudaFuncSetAttribute(gemm_min_kernel, cudaFuncAttributeMaxDynamicSharedMemorySize,
                             DYN_SMEM);
        attr_set = true;
    }
    dim3 grid(Mm / BM, NSPLIT);  // 32 x 32 = 1024 CTAs
    gemm_min_kernel<<<grid, THREADS, DYN_SMEM>>>(tmA, tmB);

    rerank_kernel<<<Mm / 8, 256>>>(z, e, out);
}

// round 17
// speedup vs baseline: 1.0816x; 1.0215x over previous
#include <cuda_runtime.h>
#include <cuda.h>
#include <cuda_fp16.h>
#include <cstdint>

// ---------------- problem constants ----------------
#define Nn 4096
#define Mm 4096
#define Dd 1024

// ---------------- GEMM tiling (round-11 champion shape, FROZEN) ----------------
#define BM 128
#define BN 128
#define BK 64                      // 64 fp16 = 128B rows (SW128 atom width)
#define KT (Dd / BK)               // 16 iterations
#define NSPLIT 32
#define STAGES 3
#define NCW 16                     // consumer warps (4m x 4n of 32x32 tiles)
#define THREADS (NCW * 32 + 32)    // +1 producer warp = 544

#define A_SZ (BM * 128)            // 16384 B
#define B_SZ (BN * 128)            // 16384 B
#define STG (A_SZ + B_SZ)          // 32768 B
#define DYN_SMEM (STAGES * STG + 1024)

// ---------------- scratch ----------------
__device__ __align__(256) __half g_zb[Nn * Dd];
__device__ __align__(256) __half g_eb[Mm * Dd];
__device__ __align__(256) float g_zsq[Nn];
__device__ __align__(256) unsigned g_rowmin[Mm];   // packed (valbits | 12-bit col)
__device__ unsigned long long g_acc;
__device__ unsigned g_cnt;

// ---------------- PTX helpers ----------------
#define MBARRIER_INIT(addr, cnt) \
    asm volatile("mbarrier.init.shared.b64 [%0], %1;" ::"r"(addr), "r"(cnt) : "memory")
#define MBARRIER_EXPECT_TX(addr, bytes) \
    asm volatile("mbarrier.arrive.expect_tx.shared.b64 _, [%0], %1;" ::"r"(addr), "r"(bytes) : "memory")
#define MBARRIER_ARRIVE(addr) \
    asm volatile("mbarrier.arrive.shared.b64 _, [%0];" ::"r"(addr) : "memory")

__device__ __forceinline__ void mbar_wait(uint32_t addr, uint32_t parity) {
    asm volatile(
        "{\n\t.reg .pred P;\n\t"
        "WL%=:\n\t"
        "mbarrier.try_wait.parity.acquire.cta.shared::cta.b64 P, [%0], %1, 0x989680;\n\t"
        "@P bra.uni WD%=;\n\t"
        "bra.uni WL%=;\n\t"
        "WD%=:\n\t}"
        ::"r"(addr), "r"(parity) : "memory");
}
__device__ __forceinline__ void mbar_wait_relaxed(uint32_t addr, uint32_t parity) {
    asm volatile(
        "{\n\t.reg .pred P;\n\t"
        "WL%=:\n\t"
        "mbarrier.try_wait.parity.relaxed.cta.shared::cta.b64 P, [%0], %1, 0x989680;\n\t"
        "@P bra.uni WD%=;\n\t"
        "bra.uni WL%=;\n\t"
        "WD%=:\n\t}"
        ::"r"(addr), "r"(parity) : "memory");
}

__device__ __forceinline__ void tma_load_2d(uint32_t smem_addr, const void* map,
                                            int cx, int cy, uint32_t mbar) {
    asm volatile(
        "cp.async.bulk.tensor.2d.shared::cta.global.tile.mbarrier::complete_tx::bytes "
        "[%0], [%1, {%2, %3}], [%4];"
        ::"r"(smem_addr), "l"(map), "r"(cx), "r"(cy), "r"(mbar)
        : "memory");
}

__device__ __forceinline__ void ldsm4(uint32_t* r, uint32_t saddr) {
    asm volatile("ldmatrix.sync.aligned.m8n8.x4.shared.b16 {%0,%1,%2,%3}, [%4];\n"
                 : "=r"(r[0]), "=r"(r[1]), "=r"(r[2]), "=r"(r[3])
                 : "r"(saddr));
}
__device__ __forceinline__ void mma16816_f16(uint32_t* c, const uint32_t* a,
                                             uint32_t b0, uint32_t b1) {
    asm volatile(
        "mma.sync.aligned.m16n8k16.row.col.f16.f16.f16.f16 "
        "{%0,%1}, {%2,%3,%4,%5}, {%6,%7}, {%0,%1};\n"
        : "+r"(c[0]), "+r"(c[1])
        : "r"(a[0]), "r"(a[1]), "r"(a[2]), "r"(a[3]), "r"(b0), "r"(b1));
}

// swizzled smem address of 16B chunk (row, cc) in a 128B-row SW128 tile
__device__ __forceinline__ uint32_t swz(uint32_t base, int row, int cc) {
    return base + ((uint32_t)row << 7) + (((uint32_t)(cc ^ (row & 7))) << 4);
}

// pack selection key: positive float bits (top 20) | 12-bit column
__device__ __forceinline__ unsigned packkey(float v, int col) {
    return (__float_as_uint(v) & 0xFFFFF000u) | (unsigned)col;
}

// ================= kernel 1: convert(fp16) + z norms + state init ==========
// 128-thread blocks (4 warps, warp-per-row) for finer scheduling granularity.
__global__ void __launch_bounds__(128) convert_kernel(const float* __restrict__ z,
                                                      const float* __restrict__ e) {
    if (blockIdx.x == 0) {
        for (int i = threadIdx.x; i < Mm; i += 128) g_rowmin[i] = 0xFFFFFFFFu;
        if (threadIdx.x == 0) { g_acc = 0ull; g_cnt = 0u; }
    }
    const int gwarp = (blockIdx.x * 128 + threadIdx.x) >> 5;
    const int lane = threadIdx.x & 31;
    const float* src;
    __half* dst;
    float* sqo = nullptr;
    if (gwarp < Nn) {
        src = z + (size_t)gwarp * Dd;
        dst = g_zb + (size_t)gwarp * Dd;
        sqo = g_zsq + gwarp;
    } else {
        const int r = gwarp - Nn;
        src = e + (size_t)r * Dd;
        dst = g_eb + (size_t)r * Dd;
    }
    const float4* s4 = reinterpret_cast<const float4*>(src);
    uint4* d4 = reinterpret_cast<uint4*>(dst);
    float4 v[8];
#pragma unroll
    for (int i = 0; i < 8; i++) v[i] = s4[2 * (lane + 32 * (i >> 1)) + (i & 1)];
    float s = 0.f;
#pragma unroll
    for (int i = 0; i < 4; i++) {
        const int idx = lane + 32 * i;
        const float4 v0 = v[2 * i];
        const float4 v1 = v[2 * i + 1];
        __half2 p0 = __floats2half2_rn(v0.x, v0.y);
        __half2 p1 = __floats2half2_rn(v0.z, v0.w);
        __half2 p2 = __floats2half2_rn(v1.x, v1.y);
        __half2 p3 = __floats2half2_rn(v1.z, v1.w);
        uint4 w;
        w.x = *reinterpret_cast<unsigned*>(&p0);
        w.y = *reinterpret_cast<unsigned*>(&p1);
        w.z = *reinterpret_cast<unsigned*>(&p2);
        w.w = *reinterpret_cast<unsigned*>(&p3);
        d4[idx] = w;
        s += v0.x * v0.x + v0.y * v0.y + v0.z * v0.z + v0.w * v0.w;
        s += v1.x * v1.x + v1.y * v1.y + v1.z * v1.z + v1.w * v1.w;
    }
    if (sqo) {
#pragma unroll
        for (int o = 16; o; o >>= 1) s += __shfl_xor_sync(0xffffffffu, s, o);
        if (lane == 0) *sqo = s;
    }
}

// ================= kernel 2: TMA-fed f16-acc GEMM + packed argmin (FROZEN) =========
__global__ void __launch_bounds__(THREADS, 2) gemm_min_kernel(
    const __grid_constant__ CUtensorMap tmA,
    const __grid_constant__ CUtensorMap tmB) {
    extern __shared__ char dyn_raw[];
    __shared__ __align__(8) uint64_t s_bar[2 * STAGES];
    __shared__ unsigned srm[4][BM];

    uint32_t dynb = (uint32_t)__cvta_generic_to_shared(dyn_raw);
    dynb = (dynb + 1023u) & ~1023u;
    const uint32_t barb = (uint32_t)__cvta_generic_to_shared(s_bar);
#define BAR_FULL(s) (barb + (uint32_t)(s) * 8u)
#define BAR_EMPTY(s) (barb + (uint32_t)(STAGES + (s)) * 8u)

    const int tid = threadIdx.x;
    const int lane = tid & 31;
    const int warp = tid >> 5;

    const int m0 = blockIdx.x * BM;
    const int n0 = blockIdx.y * BN;

    if (tid == 0) {
#pragma unroll
        for (int s = 0; s < STAGES; s++) {
            MBARRIER_INIT(BAR_FULL(s), 1);
            MBARRIER_INIT(BAR_EMPTY(s), NCW);
        }
    }
    __syncthreads();

    if (warp < NCW) {
        // ---------------- consumers ----------------
        const int wm = warp >> 2;        // 0..3 : 32-row group
        const int wn = warp & 3;         // 0..3 : 32-col group
        const int ldrow = lane & 15;
        const int ldcc = lane >> 4;

        uint32_t acc[2][4][2];           // f16x2 accumulators (16 regs)
#pragma unroll
        for (int mi = 0; mi < 2; mi++)
#pragma unroll
            for (int g = 0; g < 4; g++) { acc[mi][g][0] = 0u; acc[mi][g][1] = 0u; }

        int slot = 0, ph = 0;
        for (int j = 0; j < KT; j++) {
            mbar_wait(BAR_FULL(slot), (uint32_t)ph);
            const uint32_t sa = dynb + slot * STG;
            const uint32_t sb = sa + A_SZ;

#pragma unroll
            for (int ks = 0; ks < 4; ks++) {
                const int cc = ks * 2 + ldcc;
                uint32_t a[2][4];
#pragma unroll
                for (int mi = 0; mi < 2; mi++)
                    ldsm4(a[mi], swz(sa, wm * 32 + mi * 16 + ldrow, cc));
                uint32_t b[2][4];
#pragma unroll
                for (int h = 0; h < 2; h++)
                    ldsm4(b[h], swz(sb, wn * 32 + h * 16 + ldrow, cc));
#pragma unroll
                for (int h = 0; h < 2; h++) {
#pragma unroll
                    for (int mi = 0; mi < 2; mi++) {
                        mma16816_f16(&acc[mi][2 * h][0], a[mi], b[h][0], b[h][2]);
                        mma16816_f16(&acc[mi][2 * h + 1][0], a[mi], b[h][1], b[h][3]);
                    }
                }
            }
            __syncwarp();
            if (lane == 0) MBARRIER_ARRIVE(BAR_EMPTY(slot));
            if (++slot == STAGES) { slot = 0; ph ^= 1; }
        }

        // ---- epilogue: packed argmin keys over this CTA's 128 columns ----
        unsigned rk0 = 0xFFFFFFFFu, rk1 = 0xFFFFFFFFu, rk2 = 0xFFFFFFFFu, rk3 = 0xFFFFFFFFu;
        const int colbase = n0 + wn * 32 + (lane & 3) * 2;
#pragma unroll
        for (int g = 0; g < 4; g++) {
            const int col = colbase + g * 8;
            const float zs0 = g_zsq[col] + 1024.f;   // shift keeps v positive
            const float zs1 = g_zsq[col + 1] + 1024.f;
#pragma unroll
            for (int mi = 0; mi < 2; mi++) {
                const __half2 h0 = *reinterpret_cast<const __half2*>(&acc[mi][g][0]);
                const __half2 h1 = *reinterpret_cast<const __half2*>(&acc[mi][g][1]);
                const unsigned kA = min(packkey(fmaf(-2.f, __low2float(h0), zs0), col),
                                        packkey(fmaf(-2.f, __high2float(h0), zs1), col + 1));
                const unsigned kB = min(packkey(fmaf(-2.f, __low2float(h1), zs0), col),
                                        packkey(fmaf(-2.f, __high2float(h1), zs1), col + 1));
                if (mi == 0) { rk0 = min(rk0, kA); rk1 = min(rk1, kB); }
                else         { rk2 = min(rk2, kA); rk3 = min(rk3, kB); }
            }
        }
#pragma unroll
        for (int off = 1; off <= 2; off <<= 1) {
            rk0 = min(rk0, __shfl_xor_sync(0xffffffffu, rk0, off));
            rk1 = min(rk1, __shfl_xor_sync(0xffffffffu, rk1, off));
            rk2 = min(rk2, __shfl_xor_sync(0xffffffffu, rk2, off));
            rk3 = min(rk3, __shfl_xor_sync(0xffffffffu, rk3, off));
        }
        if ((lane & 3) == 0) {
            const int q = lane >> 2;
            srm[wn][wm * 32 + q] = rk0;
            srm[wn][wm * 32 + q + 8] = rk1;
            srm[wn][wm * 32 + 16 + q] = rk2;
            srm[wn][wm * 32 + 24 + q] = rk3;
        }
    } else if (lane == 0) {
        // ---------------- producer (warp 16, lane 0) ----------------
        int slot = 0, ph = 1;
        for (int j = 0; j < KT; j++) {
            mbar_wait_relaxed(BAR_EMPTY(slot), (uint32_t)ph);
            MBARRIER_EXPECT_TX(BAR_FULL(slot), STG);
            const uint32_t sa = dynb + slot * STG;
            tma_load_2d(sa, &tmA, j * BK, m0, BAR_FULL(slot));
            tma_load_2d(sa + A_SZ, &tmB, j * BK, n0, BAR_FULL(slot));
            if (++slot == STAGES) { slot = 0; ph ^= 1; }
        }
    }

    __syncthreads();
    if (tid < BM) {
        const unsigned k = min(min(srm[0][tid], srm[1][tid]), min(srm[2][tid], srm[3][tid]));
        atomicMin(&g_rowmin[m0 + tid], k);
    }
}

// ================= kernel 3: exact rerank + fused deterministic sum =================
// 128-thread blocks (4 warps, warp-per-code) for finer tail packing.
__global__ void __launch_bounds__(128) rerank_kernel(const float* __restrict__ z,
                                                     const float* __restrict__ e,
                                                     float* __restrict__ out) {
    const int warp = threadIdx.x >> 5;
    const int lane = threadIdx.x & 31;
    const int m = blockIdx.x * 4 + warp;

    const int col = (int)(g_rowmin[m] & 0xFFFu);
    const float4* zp = reinterpret_cast<const float4*>(z + (size_t)col * Dd);
    const float4* ep = reinterpret_cast<const float4*>(e + (size_t)m * Dd);
    float d = 0.f;
#pragma unroll
    for (int i = 0; i < 8; i++) {
        const float4 a = zp[lane + 32 * i];
        const float4 b = ep[lane + 32 * i];
        const float dx = a.x - b.x, dy = a.y - b.y, dz = a.z - b.z, dw = a.w - b.w;
        d += dx * dx + dy * dy + dz * dz + dw * dw;
    }
#pragma unroll
    for (int o = 16; o; o >>= 1) d += __shfl_xor_sync(0xffffffffu, d, o);

    __shared__ float wsum[4];
    if (lane == 0) wsum[warp] = d;
    __syncthreads();
    if (threadIdx.x == 0) {
        float blk = wsum[0] + wsum[1] + wsum[2] + wsum[3];
        // deterministic fixed-point accumulation (2^-24)
        atomicAdd(&g_acc, (unsigned long long)__double2ll_rn((double)blk * 16777216.0));
        __threadfence();
        const unsigned done = atomicAdd(&g_cnt, 1u);
        if (done == (Mm / 4) - 1) {
            const unsigned long long tot = atomicAdd(&g_acc, 0ull);
            out[0] = (float)((double)tot / 16777216.0 / (double)Mm);
        }
    }
}

// ================= host side =================
typedef CUresult (*EncodeTiledFn)(CUtensorMap*, CUtensorMapDataType, cuuint32_t, void*,
                                  const cuuint64_t*, const cuuint64_t*, const cuuint32_t*,
                                  const cuuint32_t*, CUtensorMapInterleave, CUtensorMapSwizzle,
                                  CUtensorMapL2promotion, CUtensorMapFloatOOBfill);

static void encode_map(EncodeTiledFn fn, CUtensorMap* tm, void* base) {
    cuuint64_t dims[2] = {(cuuint64_t)Dd, (cuuint64_t)Nn};
    cuuint64_t strides[1] = {(cuuint64_t)Dd * 2};
    cuuint32_t box[2] = {(cuuint32_t)BK, (cuuint32_t)BM};
    cuuint32_t estr[2] = {1, 1};
    fn(tm, CU_TENSOR_MAP_DATA_TYPE_FLOAT16, 2, base, dims, strides, box, estr,
       CU_TENSOR_MAP_INTERLEAVE_NONE, CU_TENSOR_MAP_SWIZZLE_128B,
       CU_TENSOR_MAP_L2_PROMOTION_L2_128B, CU_TENSOR_MAP_FLOAT_OOB_FILL_NONE);
}

extern "C" void kernel_launch(void* const* d_in, const int* in_sizes, int n_in,
                              void* d_out, int out_size) {
    const float* z = (const float*)d_in[0];  // [4096, 1024]
    const float* e = (const float*)d_in[1];  // [4096, 1024]
    float* out = (float*)d_out;              // [1]

    EncodeTiledFn enc = nullptr;
    {
        void* fn = nullptr;
#if CUDART_VERSION >= 12050
        cudaDriverEntryPointQueryResult qr;
        cudaGetDriverEntryPointByVersion("cuTensorMapEncodeTiled", &fn, 12000,
                                         cudaEnableDefault, &qr);
#else
        cudaGetDriverEntryPoint("cuTensorMapEncodeTiled", &fn, cudaEnableDefault);
#endif
        enc = (EncodeTiledFn)fn;
    }
    void *pe = nullptr, *pz = nullptr;
    cudaGetSymbolAddress(&pe, g_eb);
    cudaGetSymbolAddress(&pz, g_zb);
    CUtensorMap tmA, tmB;
    encode_map(enc, &tmA, pe);
    encode_map(enc, &tmB, pz);

    convert_kernel<<<(Nn + Mm) / 4, 128>>>(z, e);

    static bool attr_set = false;
    if (!attr_set) {
        cudaFuncSetAttribute(gemm_min_kernel, cudaFuncAttributeMaxDynamicSharedMemorySize,
                             DYN_SMEM);
        attr_set = true;
    }
    dim3 grid(Mm / BM, NSPLIT);  // 32 x 32 = 1024 CTAs
    gemm_min_kernel<<<grid, THREADS, DYN_SMEM>>>(tmA, tmB);

    rerank_kernel<<<Mm / 4, 128>>>(z, e, out);
}